// round 13
// baseline (speedup 1.0000x reference)
#include <cuda_runtime.h>
#include <cuda_fp16.h>
#include <math.h>
#include <stdint.h>

// Problem constants
#define BZ       16
#define SEG_LEN  16
#define NUM_SEGS 256
#define HH       512
#define NHH      8
#define HD       64
#define SS       4097                 // NUM_SEGS*SEG_LEN + 1
#define NSEG     (BZ * NUM_SEGS)     // 4096
#define LL       18                  // SEG_LEN + 2
#define CTOK     (NSEG * SEG_LEN)    // 65536 core tokens
#define FTOK     (BZ * SS)           // 65552 (FFN tokens)
#define QKVW     (3 * HH)            // 1536
#define LN_EPS   1e-5f

// ---------------- scratch (__device__ globals) -------------------------------
__device__ __half g_core[(size_t)CTOK * HH];
__device__ __half g_qkv [(size_t)CTOK * QKVW];
__device__ __half g_att [(size_t)CTOK * HH];
__device__ __half g_o   [(size_t)CTOK * HH];
__device__ __half g_proc[(size_t)FTOK * HH];
__device__ __half g_act [(size_t)FTOK * 2 * HH];
__device__ __half g_mqkv[2 * QKVW];        // marker (start,end) q|k|v
// transposed fp16 weights [N][K] row-major
__device__ __half g_wqkvt[QKVW * HH];      // rows: 0-511 Wq^T, 512-1023 Wk^T, 1024-1535 Wv^T
__device__ __half g_wot[HH * HH];
__device__ __half g_w1t[2 * HH * HH];
__device__ __half g_w2t[2 * HH * HH];
__device__ float  g_bqkv[QKVW];

// ---------------- core tokens: fp32 hid -> fp16, drop tail token -------------
__global__ void core_convert_kernel(const float* __restrict__ hid) {
    size_t i4 = (size_t)blockIdx.x * blockDim.x + threadIdx.x;  // over CTOK*128
    int r  = (int)(i4 >> 7);
    int c4 = (int)(i4 & 127);
    int b = r >> 12, tok = r & 4095;
    float4 vv = *(const float4*)(hid + ((size_t)b * SS + tok) * HH + c4 * 4);
    __half2* dst = (__half2*)g_core + i4 * 2;
    dst[0] = __floats2half2_rn(vv.x, vv.y);
    dst[1] = __floats2half2_rn(vv.z, vv.w);
}

// ---------------- marker qkv: 2 rows x 1536, from fp32 weights ---------------
__global__ __launch_bounds__(256)
void marker_qkv_kernel(const float* __restrict__ st, const float* __restrict__ en,
                       const float* __restrict__ Wq, const float* __restrict__ bq,
                       const float* __restrict__ Wk, const float* __restrict__ bk,
                       const float* __restrict__ Wv, const float* __restrict__ bv) {
    int idx = blockIdx.x * 256 + threadIdx.x;   // 0..3071
    int row = idx / QKVW;
    int col = idx % QKVW;
    const float* in = row ? en : st;
    const float* W; const float* bb; int c = col & (HH - 1);
    if (col < HH)            { W = Wq; bb = bq; }
    else if (col < 2 * HH)   { W = Wk; bb = bk; }
    else                     { W = Wv; bb = bv; }
    float s = 0.f;
#pragma unroll 8
    for (int k = 0; k < HH; k++) s = fmaf(in[k], W[k * HH + c], s);
    g_mqkv[row * QKVW + col] = __float2half_rn(s + bb[c]);
}

// ---------------- batched 512x512 transposes: {Wq,Wk,Wv,Wo} ------------------
__global__ __launch_bounds__(256)
void transpose4_kernel(const float* __restrict__ Wq, const float* __restrict__ Wk,
                       const float* __restrict__ Wv, const float* __restrict__ Wo) {
    __shared__ float t[32][33];
    int z = blockIdx.z;
    const float* src = (z == 0) ? Wq : (z == 1) ? Wk : (z == 2) ? Wv : Wo;
    __half* dst = (z < 3) ? (g_wqkvt + (size_t)z * HH * HH) : g_wot;
    int nb = blockIdx.x * 32, kb = blockIdx.y * 32;
    int tx = threadIdx.x & 31, ty = threadIdx.x >> 5;  // 32 x 8
#pragma unroll
    for (int i = 0; i < 32; i += 8)
        t[ty + i][tx] = src[(size_t)(kb + ty + i) * HH + nb + tx];
    __syncthreads();
#pragma unroll
    for (int i = 0; i < 32; i += 8)
        dst[(size_t)(nb + ty + i) * HH + kb + tx] = __float2half_rn(t[tx][ty + i]);
}

// ---------------- weight transpose+convert: src[K][N] f32 -> dst[N][K] f16 ---
__global__ __launch_bounds__(256)
void transpose_kernel(const float* __restrict__ src, __half* __restrict__ dst,
                      int K, int N) {
    __shared__ float t[32][33];
    int nb = blockIdx.x * 32, kb = blockIdx.y * 32;
    int tx = threadIdx.x & 31, ty = threadIdx.x >> 5;  // 32 x 8
#pragma unroll
    for (int i = 0; i < 32; i += 8)
        t[ty + i][tx] = src[(size_t)(kb + ty + i) * N + nb + tx];
    __syncthreads();
#pragma unroll
    for (int i = 0; i < 32; i += 8)
        dst[(size_t)(nb + ty + i) * K + kb + tx] = __float2half_rn(t[tx][ty + i]);
}

// ---------------- FP16 tensor-core GEMM (m16n8k16 + ldmatrix) ----------------
// 256 threads, 8 warps (64x32 warp tiles), 5-stage cp.async, issue hoisted
// ahead of compute so next-stage loads overlap the mma work.
// C[M,N] = A[M,K] @ Wt[N,K]^T + bias (+epilogue)
// EPI: 0 = +bias ; 1 = gelu(x+bias) ; 2 = x+bias+res
__device__ __forceinline__ float gelu_exact(float x) {
    return 0.5f * x * (1.0f + erff(x * 0.70710678118654752f));
}
__device__ __forceinline__ uint32_t s2u(const void* p) {
    return (uint32_t)__cvta_generic_to_shared(p);
}
__device__ __forceinline__ void cpa16h(__half* smem_dst, const __half* gsrc) {
    uint32_t s = s2u(smem_dst);
    asm volatile("cp.async.cg.shared.global [%0], [%1], 16;\n" :: "r"(s), "l"(gsrc));
}

#define ASTRH   40                        // smem row stride in halves (80B: 5r mod 8 banks)
#define OP_STG  (128 * ASTRH)             // halves per operand per stage
#define HNSTG   5
#define GEMM_SMEM (2 * HNSTG * OP_STG * 2)   // 102,400 bytes

#define LDMX4(r0, r1, r2, r3, addr) \
    asm volatile("ldmatrix.sync.aligned.m8n8.x4.shared.b16 {%0,%1,%2,%3}, [%4];" \
                 : "=r"(r0), "=r"(r1), "=r"(r2), "=r"(r3) : "r"(addr))

template <int EPI, typename OutT>
__global__ __launch_bounds__(256, 2)
void hgemm_kernel(const __half* __restrict__ A, const __half* __restrict__ W,
                  const float* __restrict__ bias, const float* __restrict__ res,
                  OutT* __restrict__ C, int M, int N, int K) {
    extern __shared__ __half sh[];
    __half* As = sh;                     // [5][128][ASTRH]
    __half* Bs = sh + HNSTG * OP_STG;    // [5][128][ASTRH]

    const int tid  = threadIdx.x;
    const int warp = tid >> 5;
    const int lane = tid & 31;
    const int g    = lane >> 2;
    const int tig  = lane & 3;
    const int m0 = blockIdx.y * 128;
    const int n0 = blockIdx.x * 128;
    const int warp_m = (warp & 1) * 64;     // 2 warps in M
    const int warp_n = (warp >> 1) * 32;    // 4 warps in N

    // loaders: 2 threads per row, 16 halves (2 x 16B) each
    int arow = m0 + (tid >> 1); if (arow > M - 1) arow = M - 1;
    const __half* Ag = A + (size_t)arow * K + (tid & 1) * 16;
    const __half* Bg = W + (size_t)(n0 + (tid >> 1)) * K + (tid & 1) * 16;
    __half* Asd = As + (tid >> 1) * ASTRH + (tid & 1) * 16;
    __half* Bsd = Bs + (tid >> 1) * ASTRH + (tid & 1) * 16;

    const int nk = K >> 5;   // BK = 32 halves

    auto issue = [&](int kt) {
        int s = kt % HNSTG;
        const __half* ga = Ag + kt * 32;
        __half* da = Asd + s * OP_STG;
        cpa16h(da, ga); cpa16h(da + 8, ga + 8);
        const __half* gb = Bg + kt * 32;
        __half* db = Bsd + s * OP_STG;
        cpa16h(db, gb); cpa16h(db + 8, gb + 8);
    };

    // ldmatrix per-lane offsets (in halves)
    const uint32_t a_off = ((lane & 7) + ((lane >> 3) & 1) * 8) * ASTRH + (lane >> 4) * 8;
    const uint32_t b_off = ((lane & 7) + ((lane >> 4) & 1) * 8) * ASTRH + ((lane >> 3) & 1) * 8;

    float acc[4][4][4];
#pragma unroll
    for (int i = 0; i < 4; i++)
#pragma unroll
        for (int j = 0; j < 4; j++)
#pragma unroll
            for (int c = 0; c < 4; c++) acc[i][j][c] = 0.f;

    // prologue: 4 stages in flight
#pragma unroll
    for (int p = 0; p < 4; p++) {
        if (p < nk) issue(p);
        asm volatile("cp.async.commit_group;" ::: "memory");
    }

    for (int kt = 0; kt < nk; kt++) {
        asm volatile("cp.async.wait_group 3;" ::: "memory");
        __syncthreads();
        // hoisted issue: stage (kt+4)%5 overwrites (kt-1)%5, whose consumers
        // all passed the barrier above; loads overlap this iteration's mma.
        if (kt + 4 < nk) issue(kt + 4);
        asm volatile("cp.async.commit_group;" ::: "memory");   // may be empty (tail)

        uint32_t asu = s2u(As + (kt % HNSTG) * OP_STG);
        uint32_t bsu = s2u(Bs + (kt % HNSTG) * OP_STG);
#pragma unroll
        for (int ks = 0; ks < 32; ks += 16) {
            uint32_t af[4][4], bf[4][2];
#pragma unroll
            for (int mt = 0; mt < 4; mt++) {
                uint32_t ad = asu + 2u * ((warp_m + mt * 16) * ASTRH + ks + a_off);
                LDMX4(af[mt][0], af[mt][1], af[mt][2], af[mt][3], ad);
            }
#pragma unroll
            for (int ntp = 0; ntp < 2; ntp++) {
                uint32_t bd = bsu + 2u * ((warp_n + ntp * 16) * ASTRH + ks + b_off);
                LDMX4(bf[ntp * 2][0], bf[ntp * 2][1],
                      bf[ntp * 2 + 1][0], bf[ntp * 2 + 1][1], bd);
            }
#pragma unroll
            for (int mt = 0; mt < 4; mt++)
#pragma unroll
                for (int nt = 0; nt < 4; nt++) {
                    asm volatile(
                        "mma.sync.aligned.m16n8k16.row.col.f32.f16.f16.f32 "
                        "{%0,%1,%2,%3}, {%4,%5,%6,%7}, {%8,%9}, {%0,%1,%2,%3};\n"
                        : "+f"(acc[mt][nt][0]), "+f"(acc[mt][nt][1]),
                          "+f"(acc[mt][nt][2]), "+f"(acc[mt][nt][3])
                        : "r"(af[mt][0]), "r"(af[mt][1]), "r"(af[mt][2]), "r"(af[mt][3]),
                          "r"(bf[nt][0]), "r"(bf[nt][1]));
                }
        }
    }

    // epilogue
#pragma unroll
    for (int nt = 0; nt < 4; nt++) {
        int col = n0 + warp_n + nt * 8 + 2 * tig;
        float bx = bias[col], by = bias[col + 1];
#pragma unroll
        for (int mt = 0; mt < 4; mt++) {
            int r0 = m0 + warp_m + mt * 16 + g;
            int r1 = r0 + 8;
            float v0 = acc[mt][nt][0] + bx, v1 = acc[mt][nt][1] + by;
            float v2 = acc[mt][nt][2] + bx, v3 = acc[mt][nt][3] + by;
            if (EPI == 1) {
                v0 = gelu_exact(v0); v1 = gelu_exact(v1);
                v2 = gelu_exact(v2); v3 = gelu_exact(v3);
            }
            if (r0 < M) {
                if (EPI == 2) {
                    const float2 rr = *(const float2*)(res + (size_t)r0 * N + col);
                    v0 += rr.x; v1 += rr.y;
                }
                OutT* p = C + (size_t)r0 * N + col;
                if (sizeof(OutT) == 2) *(__half2*)p = __floats2half2_rn(v0, v1);
                else                   *(float2*)p  = make_float2(v0, v1);
            }
            if (r1 < M) {
                if (EPI == 2) {
                    const float2 rr = *(const float2*)(res + (size_t)r1 * N + col);
                    v2 += rr.x; v3 += rr.y;
                }
                OutT* p = C + (size_t)r1 * N + col;
                if (sizeof(OutT) == 2) *(__half2*)p = __floats2half2_rn(v2, v3);
                else                   *(float2*)p  = make_float2(v2, v3);
            }
        }
    }
}

// ---------------- attention per (segment, head), core-only output ------------
#define PSTR 65   // padded smem row stride (floats)

__global__ __launch_bounds__(128)
void attn_kernel(const __half* __restrict__ qkv, const __half* __restrict__ mqkv,
                 __half* __restrict__ out) {
    const int n = blockIdx.x >> 3;
    const int h = blockIdx.x & 7;
    __shared__ float qs[LL * PSTR], ks[LL * PSTR], vs[LL * PSTR];
    __shared__ float sc[SEG_LEN][LL];

    // load 18 rows: 0=marker start, 1..16 core (qkv rows n*16..n*16+15), 17=marker end
    for (int i = threadIdx.x; i < LL * 8; i += 128) {
        int r = i >> 3, c8 = i & 7;
        const __half* src;
        if (r == 0)            src = mqkv + h * HD + c8 * 8;
        else if (r == LL - 1)  src = mqkv + QKVW + h * HD + c8 * 8;
        else                   src = qkv + ((size_t)n * 16 + (r - 1)) * QKVW + h * HD + c8 * 8;
        uint4 qv = *(const uint4*)(src);
        uint4 kv = *(const uint4*)(src + HH);
        uint4 vv = *(const uint4*)(src + 2 * HH);
        float* qd = &qs[r * PSTR + c8 * 8];
        float* kd = &ks[r * PSTR + c8 * 8];
        float* vd = &vs[r * PSTR + c8 * 8];
        const uint32_t* qw = (const uint32_t*)&qv;
        const uint32_t* kw = (const uint32_t*)&kv;
        const uint32_t* vw = (const uint32_t*)&vv;
#pragma unroll
        for (int j = 0; j < 4; j++) {
            float2 f;
            f = __half22float2(*(const __half2*)&qw[j]); qd[j*2] = f.x; qd[j*2+1] = f.y;
            f = __half22float2(*(const __half2*)&kw[j]); kd[j*2] = f.x; kd[j*2+1] = f.y;
            f = __half22float2(*(const __half2*)&vw[j]); vd[j*2] = f.x; vd[j*2+1] = f.y;
        }
    }
    __syncthreads();

    // scores only for core query rows (1..16): 16 x 18
    for (int s = threadIdx.x; s < SEG_LEN * LL; s += 128) {
        int qi = s / LL, kj = s % LL;
        float d = 0.f;
#pragma unroll
        for (int c = 0; c < HD; c++) d = fmaf(qs[(qi + 1) * PSTR + c], ks[kj * PSTR + c], d);
        sc[qi][kj] = d * 0.125f;  // 1/sqrt(64)
    }
    __syncthreads();

    if (threadIdx.x < SEG_LEN) {
        int r = threadIdx.x;
        float m = -1e30f;
#pragma unroll
        for (int j = 0; j < LL; j++) m = fmaxf(m, sc[r][j]);
        float sum = 0.f;
#pragma unroll
        for (int j = 0; j < LL; j++) { float e = __expf(sc[r][j] - m); sc[r][j] = e; sum += e; }
        float inv = 1.f / sum;
#pragma unroll
        for (int j = 0; j < LL; j++) sc[r][j] *= inv;
    }
    __syncthreads();

    for (int s = threadIdx.x; s < SEG_LEN * HD; s += 128) {
        int qi = s >> 6, d = s & 63;
        float a = 0.f;
#pragma unroll
        for (int j = 0; j < LL; j++) a = fmaf(sc[qi][j], vs[j * PSTR + d], a);
        out[((size_t)n * 16 + qi) * HH + h * HD + d] = __float2half_rn(a);
    }
}

// ---------------- LayerNorm (fp16 in) + scatter to fp16 proc -----------------
__global__ __launch_bounds__(256)
void ln_scatter_kernel(const __half* __restrict__ o, const float* __restrict__ gg,
                       const float* __restrict__ bb, __half* __restrict__ proc) {
    const int row = blockIdx.x;   // 0..CTOK-1
    const __half* x = o + (size_t)row * HH;
    const int t = threadIdx.x;
    float v0 = __half2float(x[t]), v1 = __half2float(x[t + 256]);
    float s = v0 + v1, ss = v0 * v0 + v1 * v1;
#pragma unroll
    for (int off = 16; off > 0; off >>= 1) {
        s  += __shfl_xor_sync(0xffffffffu, s,  off);
        ss += __shfl_xor_sync(0xffffffffu, ss, off);
    }
    __shared__ float sh_s[8], sh_ss[8];
    __shared__ float sh_mu, sh_inv;
    if ((t & 31) == 0) { sh_s[t >> 5] = s; sh_ss[t >> 5] = ss; }
    __syncthreads();
    if (t == 0) {
        float ts = 0.f, tss = 0.f;
#pragma unroll
        for (int w = 0; w < 8; w++) { ts += sh_s[w]; tss += sh_ss[w]; }
        float mu = ts / (float)HH;
        float var = tss / (float)HH - mu * mu;
        sh_mu = mu;
        sh_inv = rsqrtf(var + LN_EPS);
    }
    __syncthreads();
    float mu = sh_mu, inv = sh_inv;

    int b = row >> 12, tok = row & 4095;
    __half* dst = proc + ((size_t)b * SS + tok) * HH;
    dst[t]       = __float2half_rn((v0 - mu) * inv * gg[t]       + bb[t]);
    dst[t + 256] = __float2half_rn((v1 - mu) * inv * gg[t + 256] + bb[t + 256]);
}

// ---------------- copy last token rows (fp32 -> fp16) ------------------------
__global__ void copy_last_kernel(const float* __restrict__ hid, __half* __restrict__ proc) {
    size_t off = ((size_t)blockIdx.x * SS + (SS - 1)) * HH;
    for (int c = threadIdx.x; c < HH; c += blockDim.x)
        proc[off + c] = __float2half_rn(hid[off + c]);
}

// ---------------- host launcher ----------------------------------------------
extern "C" void kernel_launch(void* const* d_in, const int* in_sizes, int n_in,
                              void* d_out, int out_size) {
    const float* hid  = (const float*)d_in[0];
    const float* st   = (const float*)d_in[3];
    const float* en   = (const float*)d_in[4];
    const float* Wq   = (const float*)d_in[5];
    const float* bq   = (const float*)d_in[6];
    const float* Wk   = (const float*)d_in[7];
    const float* bk   = (const float*)d_in[8];
    const float* Wv   = (const float*)d_in[9];
    const float* bv   = (const float*)d_in[10];
    const float* Wo   = (const float*)d_in[11];
    const float* bo   = (const float*)d_in[12];
    const float* lng  = (const float*)d_in[13];
    const float* lnb  = (const float*)d_in[14];
    const float* W1   = (const float*)d_in[15];
    const float* b1   = (const float*)d_in[16];
    const float* W2   = (const float*)d_in[17];
    const float* b2   = (const float*)d_in[18];
    float* out = (float*)d_out;

    __half *qkv, *att, *o, *proc, *act, *mqkv;
    __half *wqkvt, *wot, *w1t, *w2t, *core;
    float  *bqkv;
    cudaGetSymbolAddress((void**)&core, g_core);
    cudaGetSymbolAddress((void**)&qkv,  g_qkv);
    cudaGetSymbolAddress((void**)&att,  g_att);
    cudaGetSymbolAddress((void**)&o,    g_o);
    cudaGetSymbolAddress((void**)&proc, g_proc);
    cudaGetSymbolAddress((void**)&act,  g_act);
    cudaGetSymbolAddress((void**)&mqkv, g_mqkv);
    cudaGetSymbolAddress((void**)&wqkvt, g_wqkvt);
    cudaGetSymbolAddress((void**)&wot,  g_wot);
    cudaGetSymbolAddress((void**)&w1t,  g_w1t);
    cudaGetSymbolAddress((void**)&w2t,  g_w2t);
    cudaGetSymbolAddress((void**)&bqkv, g_bqkv);

    cudaFuncSetAttribute((const void*)hgemm_kernel<0, __half>,
                         cudaFuncAttributeMaxDynamicSharedMemorySize, GEMM_SMEM);
    cudaFuncSetAttribute((const void*)hgemm_kernel<1, __half>,
                         cudaFuncAttributeMaxDynamicSharedMemorySize, GEMM_SMEM);
    cudaFuncSetAttribute((const void*)hgemm_kernel<2, float>,
                         cudaFuncAttributeMaxDynamicSharedMemorySize, GEMM_SMEM);

    // 0. weight prep + marker projections
    transpose4_kernel<<<dim3(16, 16, 4), 256>>>(Wq, Wk, Wv, Wo);
    transpose_kernel<<<dim3(32, 16), 256>>>(W1, w1t, HH, 2 * HH);
    transpose_kernel<<<dim3(16, 32), 256>>>(W2, w2t, 2 * HH, HH);
    cudaMemcpyAsync(bqkv,          bq, HH * sizeof(float), cudaMemcpyDeviceToDevice);
    cudaMemcpyAsync(bqkv + HH,     bk, HH * sizeof(float), cudaMemcpyDeviceToDevice);
    cudaMemcpyAsync(bqkv + 2 * HH, bv, HH * sizeof(float), cudaMemcpyDeviceToDevice);
    marker_qkv_kernel<<<12, 256>>>(st, en, Wq, bq, Wk, bk, Wv, bv);

    // 1. core tokens fp32 -> fp16
    core_convert_kernel<<<(CTOK * 128) / 256, 256>>>(hid);

    // 2. fused QKV projection over core tokens: [65536,512] @ [512,1536]
    dim3 gqkv(QKVW / 128, CTOK / 128);   // (12, 512)
    hgemm_kernel<0, __half><<<gqkv, 256, GEMM_SMEM>>>(core, wqkvt, bqkv, nullptr, qkv, CTOK, QKVW, HH);

    // 3. per-(segment, head) attention
    attn_kernel<<<NSEG * NHH, 128>>>(qkv, mqkv, att);

    // 4. output projection
    dim3 go(HH / 128, CTOK / 128);       // (4, 512)
    hgemm_kernel<0, __half><<<go, 256, GEMM_SMEM>>>(att, wot, bo, nullptr, o, CTOK, HH, HH);

    // 5. LayerNorm + scatter, untouched tail token rows
    ln_scatter_kernel<<<CTOK, 256>>>(o, lng, lnb, proc);
    copy_last_kernel<<<BZ, 128>>>(hid, proc);

    // 6. FFN
    dim3 gf1(2 * HH / 128, (FTOK + 127) / 128);  // (8, 513)
    hgemm_kernel<1, __half><<<gf1, 256, GEMM_SMEM>>>(proc, w1t, b1, nullptr, act, FTOK, 2 * HH, HH);
    dim3 gf2(HH / 128, (FTOK + 127) / 128);      // (4, 513)
    hgemm_kernel<2, float><<<gf2, 256, GEMM_SMEM>>>(act, w2t, b2, hid, out, FTOK, HH, 2 * HH);
}

// round 15
// speedup vs baseline: 1.0490x; 1.0490x over previous
#include <cuda_runtime.h>
#include <cuda_fp16.h>
#include <math.h>
#include <stdint.h>

// Problem constants
#define BZ       16
#define SEG_LEN  16
#define NUM_SEGS 256
#define HH       512
#define NHH      8
#define HD       64
#define SS       4097                 // NUM_SEGS*SEG_LEN + 1
#define NSEG     (BZ * NUM_SEGS)     // 4096
#define LL       18                  // SEG_LEN + 2
#define CTOK     (NSEG * SEG_LEN)    // 65536 core tokens
#define FTOK     (BZ * SS)           // 65552 (FFN tokens)
#define QKVW     (3 * HH)            // 1536
#define LN_EPS   1e-5f

// ---------------- scratch (__device__ globals) -------------------------------
__device__ __half g_core[(size_t)CTOK * HH];
__device__ __half g_qkv [(size_t)CTOK * QKVW];
__device__ __half g_att [(size_t)CTOK * HH];
__device__ __half g_o   [(size_t)CTOK * HH];
__device__ __half g_proc[(size_t)FTOK * HH];
__device__ __half g_act [(size_t)FTOK * 2 * HH];
__device__ __half g_mqkv[2 * QKVW];        // marker (start,end) q|k|v
// transposed fp16 weights [N][K] row-major
__device__ __half g_wqkvt[QKVW * HH];      // rows: 0-511 Wq^T, 512-1023 Wk^T, 1024-1535 Wv^T
__device__ __half g_wot[HH * HH];
__device__ __half g_w1t[2 * HH * HH];
__device__ __half g_w2t[2 * HH * HH];
__device__ float  g_bqkv[QKVW];

// ---------------- core tokens: fp32 hid -> fp16, drop tail token -------------
__global__ void core_convert_kernel(const float* __restrict__ hid) {
    size_t i4 = (size_t)blockIdx.x * blockDim.x + threadIdx.x;  // over CTOK*128
    int r  = (int)(i4 >> 7);
    int c4 = (int)(i4 & 127);
    int b = r >> 12, tok = r & 4095;
    float4 vv = *(const float4*)(hid + ((size_t)b * SS + tok) * HH + c4 * 4);
    __half2* dst = (__half2*)g_core + i4 * 2;
    dst[0] = __floats2half2_rn(vv.x, vv.y);
    dst[1] = __floats2half2_rn(vv.z, vv.w);
}

// ---------------- marker qkv v2: warp-per-output, coalesced ------------------
// 3072 outputs (2 markers x 1536 cols); warp w of block b handles output
// idx = b*8 + w. Lanes split K (coalesced reads of wqkvt row), shuffle-reduce.
__global__ __launch_bounds__(256)
void marker_qkv_kernel(const float* __restrict__ st, const float* __restrict__ en) {
    int idx = blockIdx.x * 8 + (threadIdx.x >> 5);   // 0..3071
    int lane = threadIdx.x & 31;
    int row = idx / QKVW;
    int col = idx % QKVW;
    const float* in = row ? en : st;
    const __half* w = g_wqkvt + (size_t)col * HH;
    float s = 0.f;
#pragma unroll
    for (int k = lane; k < HH; k += 32)
        s = fmaf(in[k], __half2float(w[k]), s);
#pragma unroll
    for (int off = 16; off > 0; off >>= 1)
        s += __shfl_xor_sync(0xffffffffu, s, off);
    if (lane == 0)
        g_mqkv[idx] = __float2half_rn(s + g_bqkv[col]);
}

// ---------------- batched 512x512 transposes: {Wq,Wk,Wv,Wo} ------------------
__global__ __launch_bounds__(256)
void transpose4_kernel(const float* __restrict__ Wq, const float* __restrict__ Wk,
                       const float* __restrict__ Wv, const float* __restrict__ Wo) {
    __shared__ float t[32][33];
    int z = blockIdx.z;
    const float* src = (z == 0) ? Wq : (z == 1) ? Wk : (z == 2) ? Wv : Wo;
    __half* dst = (z < 3) ? (g_wqkvt + (size_t)z * HH * HH) : g_wot;
    int nb = blockIdx.x * 32, kb = blockIdx.y * 32;
    int tx = threadIdx.x & 31, ty = threadIdx.x >> 5;  // 32 x 8
#pragma unroll
    for (int i = 0; i < 32; i += 8)
        t[ty + i][tx] = src[(size_t)(kb + ty + i) * HH + nb + tx];
    __syncthreads();
#pragma unroll
    for (int i = 0; i < 32; i += 8)
        dst[(size_t)(nb + ty + i) * HH + kb + tx] = __float2half_rn(t[tx][ty + i]);
}

// ---------------- weight transpose+convert: src[K][N] f32 -> dst[N][K] f16 ---
__global__ __launch_bounds__(256)
void transpose_kernel(const float* __restrict__ src, __half* __restrict__ dst,
                      int K, int N) {
    __shared__ float t[32][33];
    int nb = blockIdx.x * 32, kb = blockIdx.y * 32;
    int tx = threadIdx.x & 31, ty = threadIdx.x >> 5;  // 32 x 8
#pragma unroll
    for (int i = 0; i < 32; i += 8)
        t[ty + i][tx] = src[(size_t)(kb + ty + i) * N + nb + tx];
    __syncthreads();
#pragma unroll
    for (int i = 0; i < 32; i += 8)
        dst[(size_t)(nb + ty + i) * K + kb + tx] = __float2half_rn(t[tx][ty + i]);
}

// ---------------- FP16 tensor-core GEMM (m16n8k16 + ldmatrix) ----------------
// R12-proven config: 256 threads, 8 warps, 64x32 warp tiles, 4-stage,
// 2 blocks/SM (16 warps).
// C[M,N] = A[M,K] @ Wt[N,K]^T + bias (+epilogue)
// EPI: 0 = +bias ; 1 = gelu(x+bias) ; 2 = x+bias+res
__device__ __forceinline__ float gelu_exact(float x) {
    return 0.5f * x * (1.0f + erff(x * 0.70710678118654752f));
}
__device__ __forceinline__ uint32_t s2u(const void* p) {
    return (uint32_t)__cvta_generic_to_shared(p);
}
__device__ __forceinline__ void cpa16h(__half* smem_dst, const __half* gsrc) {
    uint32_t s = s2u(smem_dst);
    asm volatile("cp.async.cg.shared.global [%0], [%1], 16;\n" :: "r"(s), "l"(gsrc));
}

#define ASTRH   40                        // smem row stride in halves (80B: 5r mod 8 banks)
#define OP_STG  (128 * ASTRH)             // halves per operand per stage
#define HNSTG   4
#define GEMM_SMEM (2 * HNSTG * OP_STG * 2)   // 81,920 bytes

#define LDMX4(r0, r1, r2, r3, addr) \
    asm volatile("ldmatrix.sync.aligned.m8n8.x4.shared.b16 {%0,%1,%2,%3}, [%4];" \
                 : "=r"(r0), "=r"(r1), "=r"(r2), "=r"(r3) : "r"(addr))

template <int EPI, typename OutT>
__global__ __launch_bounds__(256, 2)
void hgemm_kernel(const __half* __restrict__ A, const __half* __restrict__ W,
                  const float* __restrict__ bias, const float* __restrict__ res,
                  OutT* __restrict__ C, int M, int N, int K) {
    extern __shared__ __half sh[];
    __half* As = sh;                     // [4][128][ASTRH]
    __half* Bs = sh + HNSTG * OP_STG;    // [4][128][ASTRH]

    const int tid  = threadIdx.x;
    const int warp = tid >> 5;
    const int lane = tid & 31;
    const int g    = lane >> 2;
    const int tig  = lane & 3;
    const int m0 = blockIdx.y * 128;
    const int n0 = blockIdx.x * 128;
    const int warp_m = (warp & 1) * 64;     // 2 warps in M
    const int warp_n = (warp >> 1) * 32;    // 4 warps in N

    // loaders: 2 threads per row, 16 halves (2 x 16B) each
    int arow = m0 + (tid >> 1); if (arow > M - 1) arow = M - 1;
    const __half* Ag = A + (size_t)arow * K + (tid & 1) * 16;
    const __half* Bg = W + (size_t)(n0 + (tid >> 1)) * K + (tid & 1) * 16;
    __half* Asd = As + (tid >> 1) * ASTRH + (tid & 1) * 16;
    __half* Bsd = Bs + (tid >> 1) * ASTRH + (tid & 1) * 16;

    const int nk = K >> 5;   // BK = 32 halves

    auto issue = [&](int kt) {
        int s = kt & 3;
        const __half* ga = Ag + kt * 32;
        __half* da = Asd + s * OP_STG;
        cpa16h(da, ga); cpa16h(da + 8, ga + 8);
        const __half* gb = Bg + kt * 32;
        __half* db = Bsd + s * OP_STG;
        cpa16h(db, gb); cpa16h(db + 8, gb + 8);
    };

    // ldmatrix per-lane offsets (in halves)
    const uint32_t a_off = ((lane & 7) + ((lane >> 3) & 1) * 8) * ASTRH + (lane >> 4) * 8;
    const uint32_t b_off = ((lane & 7) + ((lane >> 4) & 1) * 8) * ASTRH + ((lane >> 3) & 1) * 8;

    float acc[4][4][4];
#pragma unroll
    for (int i = 0; i < 4; i++)
#pragma unroll
        for (int j = 0; j < 4; j++)
#pragma unroll
            for (int c = 0; c < 4; c++) acc[i][j][c] = 0.f;

    // prologue: 3 stages in flight
#pragma unroll
    for (int p = 0; p < 3; p++) {
        issue(p);
        asm volatile("cp.async.commit_group;" ::: "memory");
    }

    for (int kt = 0; kt < nk; kt++) {
        asm volatile("cp.async.wait_group 2;" ::: "memory");
        __syncthreads();
        uint32_t asu = s2u(As + (kt & 3) * OP_STG);
        uint32_t bsu = s2u(Bs + (kt & 3) * OP_STG);
#pragma unroll
        for (int ks = 0; ks < 32; ks += 16) {
            uint32_t af[4][4], bf[4][2];
#pragma unroll
            for (int mt = 0; mt < 4; mt++) {
                uint32_t ad = asu + 2u * ((warp_m + mt * 16) * ASTRH + ks + a_off);
                LDMX4(af[mt][0], af[mt][1], af[mt][2], af[mt][3], ad);
            }
#pragma unroll
            for (int ntp = 0; ntp < 2; ntp++) {
                uint32_t bd = bsu + 2u * ((warp_n + ntp * 16) * ASTRH + ks + b_off);
                LDMX4(bf[ntp * 2][0], bf[ntp * 2][1],
                      bf[ntp * 2 + 1][0], bf[ntp * 2 + 1][1], bd);
            }
#pragma unroll
            for (int mt = 0; mt < 4; mt++)
#pragma unroll
                for (int nt = 0; nt < 4; nt++) {
                    asm volatile(
                        "mma.sync.aligned.m16n8k16.row.col.f32.f16.f16.f32 "
                        "{%0,%1,%2,%3}, {%4,%5,%6,%7}, {%8,%9}, {%0,%1,%2,%3};\n"
                        : "+f"(acc[mt][nt][0]), "+f"(acc[mt][nt][1]),
                          "+f"(acc[mt][nt][2]), "+f"(acc[mt][nt][3])
                        : "r"(af[mt][0]), "r"(af[mt][1]), "r"(af[mt][2]), "r"(af[mt][3]),
                          "r"(bf[nt][0]), "r"(bf[nt][1]));
                }
        }
        if (kt + 3 < nk) issue(kt + 3);
        asm volatile("cp.async.commit_group;" ::: "memory");   // may be empty (tail)
    }

    // epilogue
#pragma unroll
    for (int nt = 0; nt < 4; nt++) {
        int col = n0 + warp_n + nt * 8 + 2 * tig;
        float bx = bias[col], by = bias[col + 1];
#pragma unroll
        for (int mt = 0; mt < 4; mt++) {
            int r0 = m0 + warp_m + mt * 16 + g;
            int r1 = r0 + 8;
            float v0 = acc[mt][nt][0] + bx, v1 = acc[mt][nt][1] + by;
            float v2 = acc[mt][nt][2] + bx, v3 = acc[mt][nt][3] + by;
            if (EPI == 1) {
                v0 = gelu_exact(v0); v1 = gelu_exact(v1);
                v2 = gelu_exact(v2); v3 = gelu_exact(v3);
            }
            if (r0 < M) {
                if (EPI == 2) {
                    const float2 rr = *(const float2*)(res + (size_t)r0 * N + col);
                    v0 += rr.x; v1 += rr.y;
                }
                OutT* p = C + (size_t)r0 * N + col;
                if (sizeof(OutT) == 2) *(__half2*)p = __floats2half2_rn(v0, v1);
                else                   *(float2*)p  = make_float2(v0, v1);
            }
            if (r1 < M) {
                if (EPI == 2) {
                    const float2 rr = *(const float2*)(res + (size_t)r1 * N + col);
                    v2 += rr.x; v3 += rr.y;
                }
                OutT* p = C + (size_t)r1 * N + col;
                if (sizeof(OutT) == 2) *(__half2*)p = __floats2half2_rn(v2, v3);
                else                   *(float2*)p  = make_float2(v2, v3);
            }
        }
    }
}

// ---------------- attention per (segment, head), core-only output ------------
#define PSTR 65   // padded smem row stride (floats)

__global__ __launch_bounds__(128)
void attn_kernel(const __half* __restrict__ qkv, const __half* __restrict__ mqkv,
                 __half* __restrict__ out) {
    const int n = blockIdx.x >> 3;
    const int h = blockIdx.x & 7;
    __shared__ float qs[LL * PSTR], ks[LL * PSTR], vs[LL * PSTR];
    __shared__ float sc[SEG_LEN][LL];

    // load 18 rows: 0=marker start, 1..16 core (qkv rows n*16..n*16+15), 17=marker end
    for (int i = threadIdx.x; i < LL * 8; i += 128) {
        int r = i >> 3, c8 = i & 7;
        const __half* src;
        if (r == 0)            src = mqkv + h * HD + c8 * 8;
        else if (r == LL - 1)  src = mqkv + QKVW + h * HD + c8 * 8;
        else                   src = qkv + ((size_t)n * 16 + (r - 1)) * QKVW + h * HD + c8 * 8;
        uint4 qv = *(const uint4*)(src);
        uint4 kv = *(const uint4*)(src + HH);
        uint4 vv = *(const uint4*)(src + 2 * HH);
        float* qd = &qs[r * PSTR + c8 * 8];
        float* kd = &ks[r * PSTR + c8 * 8];
        float* vd = &vs[r * PSTR + c8 * 8];
        const uint32_t* qw = (const uint32_t*)&qv;
        const uint32_t* kw = (const uint32_t*)&kv;
        const uint32_t* vw = (const uint32_t*)&vv;
#pragma unroll
        for (int j = 0; j < 4; j++) {
            float2 f;
            f = __half22float2(*(const __half2*)&qw[j]); qd[j*2] = f.x; qd[j*2+1] = f.y;
            f = __half22float2(*(const __half2*)&kw[j]); kd[j*2] = f.x; kd[j*2+1] = f.y;
            f = __half22float2(*(const __half2*)&vw[j]); vd[j*2] = f.x; vd[j*2+1] = f.y;
        }
    }
    __syncthreads();

    // scores only for core query rows (1..16): 16 x 18
    for (int s = threadIdx.x; s < SEG_LEN * LL; s += 128) {
        int qi = s / LL, kj = s % LL;
        float d = 0.f;
#pragma unroll
        for (int c = 0; c < HD; c++) d = fmaf(qs[(qi + 1) * PSTR + c], ks[kj * PSTR + c], d);
        sc[qi][kj] = d * 0.125f;  // 1/sqrt(64)
    }
    __syncthreads();

    if (threadIdx.x < SEG_LEN) {
        int r = threadIdx.x;
        float m = -1e30f;
#pragma unroll
        for (int j = 0; j < LL; j++) m = fmaxf(m, sc[r][j]);
        float sum = 0.f;
#pragma unroll
        for (int j = 0; j < LL; j++) { float e = __expf(sc[r][j] - m); sc[r][j] = e; sum += e; }
        float inv = 1.f / sum;
#pragma unroll
        for (int j = 0; j < LL; j++) sc[r][j] *= inv;
    }
    __syncthreads();

    for (int s = threadIdx.x; s < SEG_LEN * HD; s += 128) {
        int qi = s >> 6, d = s & 63;
        float a = 0.f;
#pragma unroll
        for (int j = 0; j < LL; j++) a = fmaf(sc[qi][j], vs[j * PSTR + d], a);
        out[((size_t)n * 16 + qi) * HH + h * HD + d] = __float2half_rn(a);
    }
}

// ---------------- LayerNorm (fp16 in) + scatter to fp16 proc -----------------
__global__ __launch_bounds__(256)
void ln_scatter_kernel(const __half* __restrict__ o, const float* __restrict__ gg,
                       const float* __restrict__ bb, __half* __restrict__ proc) {
    const int row = blockIdx.x;   // 0..CTOK-1
    const __half* x = o + (size_t)row * HH;
    const int t = threadIdx.x;
    float v0 = __half2float(x[t]), v1 = __half2float(x[t + 256]);
    float s = v0 + v1, ss = v0 * v0 + v1 * v1;
#pragma unroll
    for (int off = 16; off > 0; off >>= 1) {
        s  += __shfl_xor_sync(0xffffffffu, s,  off);
        ss += __shfl_xor_sync(0xffffffffu, ss, off);
    }
    __shared__ float sh_s[8], sh_ss[8];
    __shared__ float sh_mu, sh_inv;
    if ((t & 31) == 0) { sh_s[t >> 5] = s; sh_ss[t >> 5] = ss; }
    __syncthreads();
    if (t == 0) {
        float ts = 0.f, tss = 0.f;
#pragma unroll
        for (int w = 0; w < 8; w++) { ts += sh_s[w]; tss += sh_ss[w]; }
        float mu = ts / (float)HH;
        float var = tss / (float)HH - mu * mu;
        sh_mu = mu;
        sh_inv = rsqrtf(var + LN_EPS);
    }
    __syncthreads();
    float mu = sh_mu, inv = sh_inv;

    int b = row >> 12, tok = row & 4095;
    __half* dst = proc + ((size_t)b * SS + tok) * HH;
    dst[t]       = __float2half_rn((v0 - mu) * inv * gg[t]       + bb[t]);
    dst[t + 256] = __float2half_rn((v1 - mu) * inv * gg[t + 256] + bb[t + 256]);
}

// ---------------- copy last token rows (fp32 -> fp16) ------------------------
__global__ void copy_last_kernel(const float* __restrict__ hid, __half* __restrict__ proc) {
    size_t off = ((size_t)blockIdx.x * SS + (SS - 1)) * HH;
    for (int c = threadIdx.x; c < HH; c += blockDim.x)
        proc[off + c] = __float2half_rn(hid[off + c]);
}

// ---------------- host launcher ----------------------------------------------
extern "C" void kernel_launch(void* const* d_in, const int* in_sizes, int n_in,
                              void* d_out, int out_size) {
    const float* hid  = (const float*)d_in[0];
    const float* st   = (const float*)d_in[3];
    const float* en   = (const float*)d_in[4];
    const float* Wq   = (const float*)d_in[5];
    const float* bq   = (const float*)d_in[6];
    const float* Wk   = (const float*)d_in[7];
    const float* bk   = (const float*)d_in[8];
    const float* Wv   = (const float*)d_in[9];
    const float* bv   = (const float*)d_in[10];
    const float* Wo   = (const float*)d_in[11];
    const float* bo   = (const float*)d_in[12];
    const float* lng  = (const float*)d_in[13];
    const float* lnb  = (const float*)d_in[14];
    const float* W1   = (const float*)d_in[15];
    const float* b1   = (const float*)d_in[16];
    const float* W2   = (const float*)d_in[17];
    const float* b2   = (const float*)d_in[18];
    float* out = (float*)d_out;

    __half *qkv, *att, *o, *proc, *act, *mqkv;
    __half *wqkvt, *wot, *w1t, *w2t, *core;
    float  *bqkv;
    cudaGetSymbolAddress((void**)&core, g_core);
    cudaGetSymbolAddress((void**)&qkv,  g_qkv);
    cudaGetSymbolAddress((void**)&att,  g_att);
    cudaGetSymbolAddress((void**)&o,    g_o);
    cudaGetSymbolAddress((void**)&proc, g_proc);
    cudaGetSymbolAddress((void**)&act,  g_act);
    cudaGetSymbolAddress((void**)&mqkv, g_mqkv);
    cudaGetSymbolAddress((void**)&wqkvt, g_wqkvt);
    cudaGetSymbolAddress((void**)&wot,  g_wot);
    cudaGetSymbolAddress((void**)&w1t,  g_w1t);
    cudaGetSymbolAddress((void**)&w2t,  g_w2t);
    cudaGetSymbolAddress((void**)&bqkv, g_bqkv);

    cudaFuncSetAttribute((const void*)hgemm_kernel<0, __half>,
                         cudaFuncAttributeMaxDynamicSharedMemorySize, GEMM_SMEM);
    cudaFuncSetAttribute((const void*)hgemm_kernel<1, __half>,
                         cudaFuncAttributeMaxDynamicSharedMemorySize, GEMM_SMEM);
    cudaFuncSetAttribute((const void*)hgemm_kernel<2, float>,
                         cudaFuncAttributeMaxDynamicSharedMemorySize, GEMM_SMEM);

    // 0. weight prep, then marker projections (reads wqkvt + bqkv)
    transpose4_kernel<<<dim3(16, 16, 4), 256>>>(Wq, Wk, Wv, Wo);
    transpose_kernel<<<dim3(32, 16), 256>>>(W1, w1t, HH, 2 * HH);
    transpose_kernel<<<dim3(16, 32), 256>>>(W2, w2t, 2 * HH, HH);
    cudaMemcpyAsync(bqkv,          bq, HH * sizeof(float), cudaMemcpyDeviceToDevice);
    cudaMemcpyAsync(bqkv + HH,     bk, HH * sizeof(float), cudaMemcpyDeviceToDevice);
    cudaMemcpyAsync(bqkv + 2 * HH, bv, HH * sizeof(float), cudaMemcpyDeviceToDevice);
    marker_qkv_kernel<<<384, 256>>>(st, en);

    // 1. core tokens fp32 -> fp16
    core_convert_kernel<<<(CTOK * 128) / 256, 256>>>(hid);

    // 2. fused QKV projection over core tokens: [65536,512] @ [512,1536]
    dim3 gqkv(QKVW / 128, CTOK / 128);   // (12, 512)
    hgemm_kernel<0, __half><<<gqkv, 256, GEMM_SMEM>>>(core, wqkvt, bqkv, nullptr, qkv, CTOK, QKVW, HH);

    // 3. per-(segment, head) attention
    attn_kernel<<<NSEG * NHH, 128>>>(qkv, mqkv, att);

    // 4. output projection
    dim3 go(HH / 128, CTOK / 128);       // (4, 512)
    hgemm_kernel<0, __half><<<go, 256, GEMM_SMEM>>>(att, wot, bo, nullptr, o, CTOK, HH, HH);

    // 5. LayerNorm + scatter, untouched tail token rows
    ln_scatter_kernel<<<CTOK, 256>>>(o, lng, lnb, proc);
    copy_last_kernel<<<BZ, 128>>>(hid, proc);

    // 6. FFN
    dim3 gf1(2 * HH / 128, (FTOK + 127) / 128);  // (8, 513)
    hgemm_kernel<1, __half><<<gf1, 256, GEMM_SMEM>>>(proc, w1t, b1, nullptr, act, FTOK, 2 * HH, HH);
    dim3 gf2(HH / 128, (FTOK + 127) / 128);      // (4, 513)
    hgemm_kernel<2, float><<<gf2, 256, GEMM_SMEM>>>(act, w2t, b2, hid, out, FTOK, HH, 2 * HH);
}